// round 2
// baseline (speedup 1.0000x reference)
#include <cuda_runtime.h>

#define BB 8
#define NN 1024
#define HH 8
#define FOO 64
#define FINN 256
#define BH (BB*HH)          // 64
#define ROWS (BH*NN)        // 65536

// ---------------- device scratch (static allocations are allowed) ----------
__device__ float g_h[ROWS * FOO];      // h[b,h,n,o]  16 MB
__device__ float g_hout[ROWS * FOO];   // per-head softmax-aggregated output, 16 MB
__device__ float g_s[ROWS];
__device__ float g_d[ROWS];
__device__ float g_E1[ROWS];
__device__ float g_E2[ROWS];
__device__ float g_P1[ROWS];
__device__ float g_P2[ROWS];
__device__ unsigned g_Abits[BB * NN * 32];   // adjacency bitmask, 1 MB

// ---------------- K0: pack adjacency to bits --------------------------------
__global__ __launch_bounds__(256) void pack_adj(const int* __restrict__ A) {
    int warp = threadIdx.x >> 5, lane = threadIdx.x & 31;
    int row = blockIdx.x * 8 + warp;          // b*NN + n  (0..8191)
    const int* arow = A + (size_t)row * NN;
    #pragma unroll 4
    for (int w = 0; w < 32; w++) {
        int v = arow[w * 32 + lane];
        unsigned bits = __ballot_sync(0xffffffffu, v > 0);
        if (lane == 0) g_Abits[row * 32 + w] = bits;
    }
}

// ---------------- K1: h = (x*Npost*e_atten) @ w -----------------------------
// grid (16 n-tiles, 8 heads, 8 batch), 256 threads, 64x64 tile, k-chunk 16
__global__ __launch_bounds__(256) void compute_h(const float* __restrict__ x,
                                                 const float* __restrict__ e_atten,
                                                 const float* __restrict__ Npost,
                                                 const float* __restrict__ w) {
    __shared__ float As[64][17];
    __shared__ float Bs[16][64];
    int n0 = blockIdx.x * 64;
    int hh = blockIdx.y;
    int b  = blockIdx.z;
    int tid = threadIdx.x;
    int ty = tid >> 4, tx = tid & 15;

    int lr = tid >> 2, lk = (tid & 3) * 4;    // A-tile loader: row lr, k lk..lk+3
    int br = tid >> 4, bc = (tid & 15) * 4;   // B-tile loader

    float c[4][4];
    #pragma unroll
    for (int i = 0; i < 4; i++)
        #pragma unroll
        for (int j = 0; j < 4; j++) c[i][j] = 0.f;

    for (int k0 = 0; k0 < FINN; k0 += 16) {
        float4 e  = *(const float4*)&e_atten[((size_t)(b * NN + n0 + lr)) * FINN + k0 + lk];
        float4 xv = *(const float4*)&x[b * FINN + k0 + lk];
        float4 np = *(const float4*)&Npost[(size_t)(n0 + lr) * FINN + k0 + lk];
        As[lr][lk + 0] = e.x * xv.x * np.x;
        As[lr][lk + 1] = e.y * xv.y * np.y;
        As[lr][lk + 2] = e.z * xv.z * np.z;
        As[lr][lk + 3] = e.w * xv.w * np.w;
        *(float4*)&Bs[br][bc] =
            *(const float4*)&w[((size_t)(hh * FINN + k0 + br)) * FOO + bc];
        __syncthreads();
        #pragma unroll
        for (int k = 0; k < 16; k++) {
            float4 bv = *(float4*)&Bs[k][tx * 4];
            float a0 = As[ty * 4 + 0][k];
            float a1 = As[ty * 4 + 1][k];
            float a2 = As[ty * 4 + 2][k];
            float a3 = As[ty * 4 + 3][k];
            c[0][0] = fmaf(a0, bv.x, c[0][0]); c[0][1] = fmaf(a0, bv.y, c[0][1]);
            c[0][2] = fmaf(a0, bv.z, c[0][2]); c[0][3] = fmaf(a0, bv.w, c[0][3]);
            c[1][0] = fmaf(a1, bv.x, c[1][0]); c[1][1] = fmaf(a1, bv.y, c[1][1]);
            c[1][2] = fmaf(a1, bv.z, c[1][2]); c[1][3] = fmaf(a1, bv.w, c[1][3]);
            c[2][0] = fmaf(a2, bv.x, c[2][0]); c[2][1] = fmaf(a2, bv.y, c[2][1]);
            c[2][2] = fmaf(a2, bv.z, c[2][2]); c[2][3] = fmaf(a2, bv.w, c[2][3]);
            c[3][0] = fmaf(a3, bv.x, c[3][0]); c[3][1] = fmaf(a3, bv.y, c[3][1]);
            c[3][2] = fmaf(a3, bv.z, c[3][2]); c[3][3] = fmaf(a3, bv.w, c[3][3]);
        }
        __syncthreads();
    }
    #pragma unroll
    for (int i = 0; i < 4; i++) {
        size_t off = ((size_t)((b * HH + hh) * NN) + n0 + ty * 4 + i) * FOO + tx * 4;
        float4 v; v.x = c[i][0]; v.y = c[i][1]; v.z = c[i][2]; v.w = c[i][3];
        *(float4*)&g_h[off] = v;
    }
}

// ---------------- K2a: s,d ---------------------------------------------------
__global__ __launch_bounds__(256) void compute_sd(const float* __restrict__ a_src,
                                                  const float* __restrict__ a_dst) {
    int warp = threadIdx.x >> 5, lane = threadIdx.x & 31;
    int row = blockIdx.x * 8 + warp;          // 0..65535 = (b*8+h)*1024+n
    int hh = (row >> 10) & 7;
    float h0 = g_h[(size_t)row * 64 + lane];
    float h1 = g_h[(size_t)row * 64 + 32 + lane];
    float s = h0 * a_src[hh * 64 + lane] + h1 * a_src[hh * 64 + 32 + lane];
    float d = h0 * a_dst[hh * 64 + lane] + h1 * a_dst[hh * 64 + 32 + lane];
    #pragma unroll
    for (int off = 16; off > 0; off >>= 1) {
        s += __shfl_xor_sync(0xffffffffu, s, off);
        d += __shfl_xor_sync(0xffffffffu, d, off);
    }
    if (lane == 0) { g_s[row] = s; g_d[row] = d; }
}

// ---------------- K2b: per-(b,h) dmax, then E1/E2/P1/P2 ---------------------
__global__ __launch_bounds__(256) void compute_EP() {
    __shared__ float red[256];
    int bh = blockIdx.x;                 // 0..63
    int tid = threadIdx.x;
    int base = bh << 10;
    float dm = -1e30f;
    #pragma unroll
    for (int k = 0; k < 4; k++) dm = fmaxf(dm, g_d[base + tid + 256 * k]);
    red[tid] = dm;
    __syncthreads();
    for (int off = 128; off > 0; off >>= 1) {
        if (tid < off) red[tid] = fmaxf(red[tid], red[tid + off]);
        __syncthreads();
    }
    float dmax = red[0];
    #pragma unroll
    for (int k = 0; k < 4; k++) {
        int i = base + tid + 256 * k;
        float dd = g_d[i] - dmax;               // <= 0
        g_E1[i] = expf(dd);
        g_E2[i] = expf(0.2f * dd);
        float t = g_s[i] + dmax;
        float C = fmaxf(t, 0.2f * t);           // lrelu(s+dmax) >= all row logits
        g_P1[i] = expf(t - C);                  // <= 1
        g_P2[i] = expf(0.2f * t - C);           // <= 1
    }
}

// ---------------- K3: masked softmax + attn @ h -----------------------------
// grid (16 n-tiles, 8 heads, 8 batch), 256 threads. 64 n-rows per block.
// weight(n,m) = adj ? max(P1[n]*E1[m], P2[n]*E2[m]) : 0   (no exp in loop)
__global__ __launch_bounds__(256) void attn_aggregate() {
    __shared__ float h_s[64][64];       // [m][o]
    __shared__ float wt_s[64][64];      // [m][n]
    __shared__ unsigned ab_s[64][33];   // bit rows, padded
    __shared__ float zpart[4][64];
    __shared__ float Zinv[64];

    int n0 = blockIdx.x << 6;
    int hh = blockIdx.y;
    int b  = blockIdx.z;
    int bh = b * 8 + hh;
    int tid = threadIdx.x;
    size_t hbase = (size_t)bh * NN * 64;

    // load adjacency bit rows for this n-tile
    for (int i = tid; i < 64 * 32; i += 256) {
        int n = i >> 5, wd = i & 31;
        ab_s[n][wd] = g_Abits[(size_t)(b * NN + n0 + n) * 32 + wd];
    }

    // gen-phase identity: thread owns column n = gn, quarter gc
    int gn = tid & 63, gc = tid >> 6;
    float p1 = g_P1[bh * NN + n0 + gn];
    float p2 = g_P2[bh * NN + n0 + gn];
    float z = 0.f;

    // acc-phase identity: thread owns output column o, row-group grp
    int o = tid & 63, grp = tid >> 6;
    float acc[16];
    #pragma unroll
    for (int j = 0; j < 16; j++) acc[j] = 0.f;

    __syncthreads();

    for (int mt = 0; mt < 16; mt++) {
        int m0 = mt << 6;
        // load h tile [64 m][64 o]
        for (int i = tid; i < 64 * 16; i += 256) {
            int m = i >> 4, oq = (i & 15) << 2;
            *(float4*)&h_s[m][oq] =
                *(const float4*)&g_h[hbase + (size_t)(m0 + m) * 64 + oq];
        }
        // generate weight tile (column gn, m = gc + 4i)
        {
            unsigned w0 = ab_s[gn][mt * 2];
            unsigned w1 = ab_s[gn][mt * 2 + 1];
            const float* e1p = &g_E1[bh * NN + m0];
            const float* e2p = &g_E2[bh * NN + m0];
            #pragma unroll
            for (int i = 0; i < 16; i++) {
                int m = gc + 4 * i;
                unsigned wdw = (i < 8) ? w0 : w1;
                int sh = m & 31;
                float v = fmaxf(p1 * e1p[m], p2 * e2p[m]);
                float wv = ((wdw >> sh) & 1u) ? v : 0.f;
                wt_s[m][gn] = wv;
                z += wv;
            }
        }
        __syncthreads();
        // accumulate: acc[j] += wt[m][grp*16+j] * h[m][o]
        #pragma unroll 4
        for (int m = 0; m < 64; m++) {
            float hv = h_s[m][o];
            #pragma unroll
            for (int j = 0; j < 16; j++)
                acc[j] = fmaf(wt_s[m][grp * 16 + j], hv, acc[j]);
        }
        __syncthreads();
    }

    // reduce row sums Z, normalize, write per-head output
    zpart[gc][gn] = z;
    __syncthreads();
    if (tid < 64) {
        float zz = zpart[0][tid] + zpart[1][tid] + zpart[2][tid] + zpart[3][tid];
        Zinv[tid] = (zz > 0.f) ? (1.f / zz) : 0.f;
    }
    __syncthreads();
    size_t obase = hbase + (size_t)n0 * 64;
    #pragma unroll
    for (int j = 0; j < 16; j++) {
        int n = grp * 16 + j;
        g_hout[obase + (size_t)n * 64 + o] = acc[j] * Zinv[n];
    }
}

// ---------------- K4: mean over heads + bias + mask -------------------------
__global__ __launch_bounds__(256) void finalize(const float* __restrict__ mask,
                                                const float* __restrict__ bias,
                                                float* __restrict__ out) {
    int idx = blockIdx.x * 256 + threadIdx.x;      // < B*N*FO
    int o = idx & 63;
    int n = (idx >> 6) & 1023;
    int b = idx >> 16;
    size_t base = ((size_t)(b * 8) * NN + n) * 64 + o;
    float s = 0.f;
    #pragma unroll
    for (int h = 0; h < 8; h++) s += g_hout[base + (size_t)h * NN * 64];
    out[idx] = (s * 0.125f + bias[o]) * mask[b * NN + n];
}

// ---------------- launch -----------------------------------------------------
extern "C" void kernel_launch(void* const* d_in, const int* in_sizes, int n_in,
                              void* d_out, int out_size) {
    const float* x       = (const float*)d_in[0];
    const int*   A       = (const int*)d_in[1];
    const float* mask    = (const float*)d_in[2];
    /* d_in[3] p_atten unused */
    const float* e_atten = (const float*)d_in[4];
    const float* Npost   = (const float*)d_in[5];
    const float* w       = (const float*)d_in[6];
    const float* a_src   = (const float*)d_in[7];
    const float* a_dst   = (const float*)d_in[8];
    const float* bias    = (const float*)d_in[9];
    float* out = (float*)d_out;

    pack_adj<<<1024, 256>>>(A);
    compute_h<<<dim3(16, 8, 8), 256>>>(x, e_atten, Npost, w);
    compute_sd<<<8192, 256>>>(a_src, a_dst);
    compute_EP<<<64, 256>>>();
    attn_aggregate<<<dim3(16, 8, 8), 256>>>();
    finalize<<<2048, 256>>>(mask, bias, out);
}

// round 3
// speedup vs baseline: 1.2525x; 1.2525x over previous
#include <cuda_runtime.h>

#define BB 8
#define NN 1024
#define HH 8
#define FOO 64
#define FINN 256
#define BH (BB*HH)          // 64
#define ROWS (BH*NN)        // 65536

typedef unsigned long long u64;

// ---------------- f32x2 helpers ---------------------------------------------
__device__ __forceinline__ u64 pk2(float lo, float hi) {
    u64 r;
    asm("mov.b64 %0, {%1, %2};" : "=l"(r)
        : "r"(__float_as_uint(lo)), "r"(__float_as_uint(hi)));
    return r;
}
__device__ __forceinline__ u64 dup2(float v) {
    u64 r;
    unsigned u = __float_as_uint(v);
    asm("mov.b64 %0, {%1, %1};" : "=l"(r) : "r"(u));
    return r;
}
__device__ __forceinline__ void upk2(float& lo, float& hi, u64 v) {
    unsigned a, b;
    asm("mov.b64 {%0, %1}, %2;" : "=r"(a), "=r"(b) : "l"(v));
    lo = __uint_as_float(a); hi = __uint_as_float(b);
}
__device__ __forceinline__ u64 fma2(u64 a, u64 b, u64 c) {
    u64 d;
    asm("fma.rn.f32x2 %0, %1, %2, %3;" : "=l"(d) : "l"(a), "l"(b), "l"(c));
    return d;
}
__device__ __forceinline__ u64 mul2(u64 a, u64 b) {
    u64 d;
    asm("mul.rn.f32x2 %0, %1, %2;" : "=l"(d) : "l"(a), "l"(b));
    return d;
}

// ---------------- device scratch --------------------------------------------
__device__ float g_h[ROWS * FOO];      // h[b,h,n,o]  16 MB
__device__ float g_hout[ROWS * FOO];   // per-head aggregated output, 16 MB
__device__ float g_s[ROWS];
__device__ float g_d[ROWS];
__device__ float2 g_E12[ROWS];         // interleaved {E1,E2} -> native f32x2 operand
__device__ float g_P1[ROWS];
__device__ float g_P2[ROWS];
__device__ unsigned g_Abits[BB * NN * 32];   // adjacency bitmask, 1 MB

// ---------------- K0: pack adjacency to bits --------------------------------
__global__ __launch_bounds__(256) void pack_adj(const int* __restrict__ A) {
    int warp = threadIdx.x >> 5, lane = threadIdx.x & 31;
    int row = blockIdx.x * 8 + warp;          // b*NN + n
    const int* arow = A + (size_t)row * NN;
    #pragma unroll 4
    for (int w = 0; w < 32; w++) {
        int v = arow[w * 32 + lane];
        unsigned bits = __ballot_sync(0xffffffffu, v > 0);
        if (lane == 0) g_Abits[row * 32 + w] = bits;
    }
}

// ---------------- K1: h = (x*Npost*e_atten) @ w  (f32x2) --------------------
__global__ __launch_bounds__(256) void compute_h(const float* __restrict__ x,
                                                 const float* __restrict__ e_atten,
                                                 const float* __restrict__ Npost,
                                                 const float* __restrict__ w) {
    __shared__ float As[64][17];
    __shared__ float Bs[16][64];
    int n0 = blockIdx.x * 64;
    int hh = blockIdx.y;
    int b  = blockIdx.z;
    int tid = threadIdx.x;
    int ty = tid >> 4, tx = tid & 15;

    int lr = tid >> 2, lk = (tid & 3) * 4;
    int br = tid >> 4, bc = (tid & 15) * 4;

    u64 c2[4][2];   // [row i][col pair p]: cols tx*4+2p, tx*4+2p+1
    #pragma unroll
    for (int i = 0; i < 4; i++) { c2[i][0] = 0ull; c2[i][1] = 0ull; }

    for (int k0 = 0; k0 < FINN; k0 += 16) {
        float4 e  = *(const float4*)&e_atten[((size_t)(b * NN + n0 + lr)) * FINN + k0 + lk];
        float4 xv = *(const float4*)&x[b * FINN + k0 + lk];
        float4 np = *(const float4*)&Npost[(size_t)(n0 + lr) * FINN + k0 + lk];
        As[lr][lk + 0] = e.x * xv.x * np.x;
        As[lr][lk + 1] = e.y * xv.y * np.y;
        As[lr][lk + 2] = e.z * xv.z * np.z;
        As[lr][lk + 3] = e.w * xv.w * np.w;
        *(float4*)&Bs[br][bc] =
            *(const float4*)&w[((size_t)(hh * FINN + k0 + br)) * FOO + bc];
        __syncthreads();
        #pragma unroll
        for (int k = 0; k < 16; k++) {
            float4 bv = *(float4*)&Bs[k][tx * 4];
            u64 b01 = pk2(bv.x, bv.y);
            u64 b23 = pk2(bv.z, bv.w);
            #pragma unroll
            for (int i = 0; i < 4; i++) {
                u64 ad = dup2(As[ty * 4 + i][k]);
                c2[i][0] = fma2(b01, ad, c2[i][0]);
                c2[i][1] = fma2(b23, ad, c2[i][1]);
            }
        }
        __syncthreads();
    }
    #pragma unroll
    for (int i = 0; i < 4; i++) {
        size_t off = ((size_t)((b * HH + hh) * NN) + n0 + ty * 4 + i) * FOO + tx * 4;
        float4 v;
        upk2(v.x, v.y, c2[i][0]);
        upk2(v.z, v.w, c2[i][1]);
        *(float4*)&g_h[off] = v;
    }
}

// ---------------- K2a: s,d ---------------------------------------------------
__global__ __launch_bounds__(256) void compute_sd(const float* __restrict__ a_src,
                                                  const float* __restrict__ a_dst) {
    int warp = threadIdx.x >> 5, lane = threadIdx.x & 31;
    int row = blockIdx.x * 8 + warp;
    int hh = (row >> 10) & 7;
    float h0 = g_h[(size_t)row * 64 + lane];
    float h1 = g_h[(size_t)row * 64 + 32 + lane];
    float s = h0 * a_src[hh * 64 + lane] + h1 * a_src[hh * 64 + 32 + lane];
    float d = h0 * a_dst[hh * 64 + lane] + h1 * a_dst[hh * 64 + 32 + lane];
    #pragma unroll
    for (int off = 16; off > 0; off >>= 1) {
        s += __shfl_xor_sync(0xffffffffu, s, off);
        d += __shfl_xor_sync(0xffffffffu, d, off);
    }
    if (lane == 0) { g_s[row] = s; g_d[row] = d; }
}

// ---------------- K2b: per-(b,h) dmax, then E12/P1/P2 -----------------------
__global__ __launch_bounds__(256) void compute_EP() {
    __shared__ float red[256];
    int bh = blockIdx.x;                 // 0..63
    int tid = threadIdx.x;
    int base = bh << 10;
    float dm = -1e30f;
    #pragma unroll
    for (int k = 0; k < 4; k++) dm = fmaxf(dm, g_d[base + tid + 256 * k]);
    red[tid] = dm;
    __syncthreads();
    for (int off = 128; off > 0; off >>= 1) {
        if (tid < off) red[tid] = fmaxf(red[tid], red[tid + off]);
        __syncthreads();
    }
    float dmax = red[0];
    #pragma unroll
    for (int k = 0; k < 4; k++) {
        int i = base + tid + 256 * k;
        float dd = g_d[i] - dmax;                       // <= 0
        g_E12[i] = make_float2(expf(dd), expf(0.2f * dd));
        float t = g_s[i] + dmax;
        float C = fmaxf(t, 0.2f * t);                   // lrelu(s+dmax) upper bound
        g_P1[i] = expf(t - C);
        g_P2[i] = expf(0.2f * t - C);
    }
}

// ---------------- K3: masked softmax + attn @ h (f32x2) ---------------------
// weight(n,m) = adj ? max(P1[n]*E1[m], P2[n]*E2[m]) : 0
__global__ __launch_bounds__(256) void attn_aggregate() {
    __shared__ float h_s[64][64];       // [m][o]
    __shared__ float wt_s[64][64];      // [m][n]
    __shared__ unsigned ab_s[64][33];
    __shared__ float zpart[4][64];
    __shared__ float Zinv[64];

    int n0 = blockIdx.x << 6;
    int hh = blockIdx.y;
    int b  = blockIdx.z;
    int bh = b * 8 + hh;
    int tid = threadIdx.x;
    size_t hbase = (size_t)bh * NN * 64;

    for (int i = tid; i < 64 * 32; i += 256) {
        int n = i >> 5, wd = i & 31;
        ab_s[n][wd] = g_Abits[(size_t)(b * NN + n0 + n) * 32 + wd];
    }

    // gen identity: column gn, quarter gc (m = gc + 4i)
    int gn = tid & 63, gc = tid >> 6;
    u64 pq = pk2(g_P1[bh * NN + n0 + gn], g_P2[bh * NN + n0 + gn]);
    float z = 0.f;

    // acc identity: 4 o-cols (4*o4..), 4 n-rows (4*grp..)
    int o4 = tid & 15, grp = tid >> 4;
    u64 acc[4][2];    // [o][n-pair]: pair holds n=4grp+2p, 4grp+2p+1
    #pragma unroll
    for (int o = 0; o < 4; o++) { acc[o][0] = 0ull; acc[o][1] = 0ull; }

    __syncthreads();

    for (int mt = 0; mt < 16; mt++) {
        int m0 = mt << 6;
        // load h tile [64 m][64 o]
        for (int i = tid; i < 64 * 16; i += 256) {
            int m = i >> 4, oq = (i & 15) << 2;
            *(float4*)&h_s[m][oq] =
                *(const float4*)&g_h[hbase + (size_t)(m0 + m) * 64 + oq];
        }
        // generate weight tile: 1 mul.f32x2 + 1 max per entry, no exp
        {
            unsigned w0 = ab_s[gn][mt * 2];
            unsigned w1 = ab_s[gn][mt * 2 + 1];
            const u64* e12 = (const u64*)&g_E12[bh * NN + m0];  // packed {E1,E2}
            #pragma unroll
            for (int i = 0; i < 16; i++) {
                int m = gc + 4 * i;
                u64 v2 = mul2(pq, e12[m]);
                float lo, hi; upk2(lo, hi, v2);
                float v = fmaxf(lo, hi);
                unsigned wdw = (i < 8) ? w0 : w1;
                float wv = ((wdw >> (m & 31)) & 1u) ? v : 0.f;
                wt_s[m][gn] = wv;
                z += wv;
            }
        }
        __syncthreads();
        // accumulate: acc[o][p] += {wt[n2p],wt[n2p+1]} * {h[o],h[o]}
        #pragma unroll 4
        for (int m = 0; m < 64; m++) {
            ulonglong2 wtp = *(const ulonglong2*)&wt_s[m][grp << 2];  // packed n-pairs
            float4 hvv = *(const float4*)&h_s[m][o4 << 2];
            u64 h0 = dup2(hvv.x), h1 = dup2(hvv.y), h2 = dup2(hvv.z), h3 = dup2(hvv.w);
            acc[0][0] = fma2(wtp.x, h0, acc[0][0]); acc[0][1] = fma2(wtp.y, h0, acc[0][1]);
            acc[1][0] = fma2(wtp.x, h1, acc[1][0]); acc[1][1] = fma2(wtp.y, h1, acc[1][1]);
            acc[2][0] = fma2(wtp.x, h2, acc[2][0]); acc[2][1] = fma2(wtp.y, h2, acc[2][1]);
            acc[3][0] = fma2(wtp.x, h3, acc[3][0]); acc[3][1] = fma2(wtp.y, h3, acc[3][1]);
        }
        __syncthreads();
    }

    // reduce row sums Z, normalize, write per-head output
    zpart[gc][gn] = z;
    __syncthreads();
    if (tid < 64) {
        float zz = zpart[0][tid] + zpart[1][tid] + zpart[2][tid] + zpart[3][tid];
        Zinv[tid] = (zz > 0.f) ? (1.f / zz) : 0.f;
    }
    __syncthreads();
    size_t obase = hbase + (size_t)n0 * 64;
    #pragma unroll
    for (int p = 0; p < 2; p++) {
        int nA = (grp << 2) + 2 * p, nB = nA + 1;
        float ziA = Zinv[nA], ziB = Zinv[nB];
        float la[4], lb[4];
        #pragma unroll
        for (int o = 0; o < 4; o++) upk2(la[o], lb[o], acc[o][p]);
        float4 va, vb;
        va.x = la[0] * ziA; va.y = la[1] * ziA; va.z = la[2] * ziA; va.w = la[3] * ziA;
        vb.x = lb[0] * ziB; vb.y = lb[1] * ziB; vb.z = lb[2] * ziB; vb.w = lb[3] * ziB;
        *(float4*)&g_hout[obase + (size_t)nA * 64 + (o4 << 2)] = va;
        *(float4*)&g_hout[obase + (size_t)nB * 64 + (o4 << 2)] = vb;
    }
}

// ---------------- K4: mean over heads + bias + mask -------------------------
__global__ __launch_bounds__(256) void finalize(const float* __restrict__ mask,
                                                const float* __restrict__ bias,
                                                float* __restrict__ out) {
    int idx = blockIdx.x * 256 + threadIdx.x;      // < B*N*FO
    int o = idx & 63;
    int n = (idx >> 6) & 1023;
    int b = idx >> 16;
    size_t base = ((size_t)(b * 8) * NN + n) * 64 + o;
    float s = 0.f;
    #pragma unroll
    for (int h = 0; h < 8; h++) s += g_hout[base + (size_t)h * NN * 64];
    out[idx] = (s * 0.125f + bias[o]) * mask[b * NN + n];
}

// ---------------- launch -----------------------------------------------------
extern "C" void kernel_launch(void* const* d_in, const int* in_sizes, int n_in,
                              void* d_out, int out_size) {
    const float* x       = (const float*)d_in[0];
    const int*   A       = (const int*)d_in[1];
    const float* mask    = (const float*)d_in[2];
    /* d_in[3] p_atten unused */
    const float* e_atten = (const float*)d_in[4];
    const float* Npost   = (const float*)d_in[5];
    const float* w       = (const float*)d_in[6];
    const float* a_src   = (const float*)d_in[7];
    const float* a_dst   = (const float*)d_in[8];
    const float* bias    = (const float*)d_in[9];
    float* out = (float*)d_out;

    pack_adj<<<1024, 256>>>(A);
    compute_h<<<dim3(16, 8, 8), 256>>>(x, e_atten, Npost, w);
    compute_sd<<<8192, 256>>>(a_src, a_dst);
    compute_EP<<<64, 256>>>();
    attn_aggregate<<<dim3(16, 8, 8), 256>>>();
    finalize<<<2048, 256>>>(mask, bias, out);
}

// round 6
// speedup vs baseline: 1.4954x; 1.1939x over previous
#include <cuda_runtime.h>

#define BB 8
#define NN 1024
#define HH 8
#define FOO 64
#define FINN 256
#define BH (BB*HH)          // 64
#define ROWS (BH*NN)        // 65536

typedef unsigned long long u64;
typedef unsigned int u32;

// ---------------- f32x2 / misc helpers --------------------------------------
__device__ __forceinline__ u64 pk2(float lo, float hi) {
    u64 r;
    asm("mov.b64 %0, {%1, %2};" : "=l"(r)
        : "r"(__float_as_uint(lo)), "r"(__float_as_uint(hi)));
    return r;
}
__device__ __forceinline__ u64 dup2(float v) {
    u64 r; u32 u = __float_as_uint(v);
    asm("mov.b64 %0, {%1, %1};" : "=l"(r) : "r"(u));
    return r;
}
__device__ __forceinline__ void upk2(float& lo, float& hi, u64 v) {
    u32 a, b;
    asm("mov.b64 {%0, %1}, %2;" : "=r"(a), "=r"(b) : "l"(v));
    lo = __uint_as_float(a); hi = __uint_as_float(b);
}
__device__ __forceinline__ u64 fma2(u64 a, u64 b, u64 c) {
    u64 d;
    asm("fma.rn.f32x2 %0, %1, %2, %3;" : "=l"(d) : "l"(a), "l"(b), "l"(c));
    return d;
}
__device__ __forceinline__ u64 mul2(u64 a, u64 b) {
    u64 d;
    asm("mul.rn.f32x2 %0, %1, %2;" : "=l"(d) : "l"(a), "l"(b));
    return d;
}
__device__ __forceinline__ u32 tf32bits(float x) {
    u32 r; asm("cvt.rn.tf32.f32 %0, %1;" : "=r"(r) : "f"(x));
    return r;
}
__device__ __forceinline__ float tf32rn(float x) {
    return __uint_as_float(tf32bits(x));
}

// warp-level tf32 mma: D(16x8) += A(16x8) * B(8x8)
__device__ __forceinline__ void mma_tf32(float* d, u32 a0, u32 a1, u32 a2, u32 a3,
                                         u32 b0, u32 b1) {
    asm volatile(
        "mma.sync.aligned.m16n8k8.row.col.f32.tf32.tf32.f32 "
        "{%0,%1,%2,%3}, {%4,%5,%6,%7}, {%8,%9}, {%0,%1,%2,%3};"
        : "+f"(d[0]), "+f"(d[1]), "+f"(d[2]), "+f"(d[3])
        : "r"(a0), "r"(a1), "r"(a2), "r"(a3), "r"(b0), "r"(b1));
}

// ---------------- device scratch --------------------------------------------
__device__ float g_hT[BH * FOO * NN];   // hT[bh][o][n]  16.8 MB
__device__ float g_hout[ROWS * FOO];    // per-head output [bh][n][o]
__device__ float g_s[ROWS];
__device__ float g_d[ROWS];
__device__ float2 g_E12[ROWS];          // {E1,E2} interleaved
__device__ float2 g_P12[ROWS];          // {P1,P2} interleaved
__device__ u32 g_Abits[BB * NN * 32];

// ---------------- K0: pack adjacency ----------------------------------------
__global__ __launch_bounds__(256) void pack_adj(const int* __restrict__ A) {
    int warp = threadIdx.x >> 5, lane = threadIdx.x & 31;
    int row = blockIdx.x * 8 + warp;
    const int* arow = A + (size_t)row * NN;
    #pragma unroll 4
    for (int w = 0; w < 32; w++) {
        int v = arow[w * 32 + lane];
        unsigned bits = __ballot_sync(0xffffffffu, v > 0);
        if (lane == 0) g_Abits[row * 32 + w] = bits;
    }
}

// ---------------- K1: hT[bh][o][n] = sum_k w[h][k][o] * recx[b][n][k] -------
__global__ __launch_bounds__(256) void compute_hT(const float* __restrict__ x,
                                                  const float* __restrict__ e_atten,
                                                  const float* __restrict__ Npost,
                                                  const float* __restrict__ w) {
    __shared__ float As[16][64];    // w[k][o]
    __shared__ float Bs[16][64];    // recx[k][n]
    int n0 = blockIdx.x * 64;
    int hh = blockIdx.y;
    int b  = blockIdx.z;
    int tid = threadIdx.x;
    int ty = tid >> 4, tx = tid & 15;         // out: o = ty*4.., n = tx*4..
    int la_k = tid >> 4, la_o = (tid & 15) * 4;
    int lb_n = tid & 63, lb_k = (tid >> 6) * 4;

    u64 c2[4][2];
    #pragma unroll
    for (int i = 0; i < 4; i++) { c2[i][0] = 0ull; c2[i][1] = 0ull; }

    for (int k0 = 0; k0 < FINN; k0 += 16) {
        *(float4*)&As[la_k][la_o] =
            *(const float4*)&w[((size_t)(hh * FINN + k0 + la_k)) * FOO + la_o];
        float4 e  = *(const float4*)&e_atten[((size_t)(b * NN + n0 + lb_n)) * FINN + k0 + lb_k];
        float4 xv = *(const float4*)&x[b * FINN + k0 + lb_k];
        float4 np = *(const float4*)&Npost[(size_t)(n0 + lb_n) * FINN + k0 + lb_k];
        Bs[lb_k + 0][lb_n] = e.x * xv.x * np.x;
        Bs[lb_k + 1][lb_n] = e.y * xv.y * np.y;
        Bs[lb_k + 2][lb_n] = e.z * xv.z * np.z;
        Bs[lb_k + 3][lb_n] = e.w * xv.w * np.w;
        __syncthreads();
        #pragma unroll
        for (int k = 0; k < 16; k++) {
            float4 bv = *(float4*)&Bs[k][tx * 4];
            u64 b01 = pk2(bv.x, bv.y);
            u64 b23 = pk2(bv.z, bv.w);
            #pragma unroll
            for (int i = 0; i < 4; i++) {
                u64 ad = dup2(As[k][ty * 4 + i]);
                c2[i][0] = fma2(b01, ad, c2[i][0]);
                c2[i][1] = fma2(b23, ad, c2[i][1]);
            }
        }
        __syncthreads();
    }
    int bh = b * HH + hh;
    #pragma unroll
    for (int i = 0; i < 4; i++) {
        size_t off = ((size_t)(bh * FOO) + ty * 4 + i) * NN + n0 + tx * 4;
        float4 v;
        upk2(v.x, v.y, c2[i][0]);
        upk2(v.z, v.w, c2[i][1]);
        *(float4*)&g_hT[off] = v;
    }
}

// ---------------- K2a: s,d from hT ------------------------------------------
__global__ __launch_bounds__(256) void compute_sd(const float* __restrict__ a_src,
                                                  const float* __restrict__ a_dst) {
    int bh = blockIdx.x >> 2;
    int n = ((blockIdx.x & 3) << 8) + threadIdx.x;
    int hh = bh & 7;
    const float* hp = &g_hT[(size_t)bh * FOO * NN + n];
    float s = 0.f, d = 0.f;
    #pragma unroll 8
    for (int o = 0; o < 64; o++) {
        float hv = hp[(size_t)o * NN];
        s = fmaf(hv, __ldg(&a_src[hh * 64 + o]), s);
        d = fmaf(hv, __ldg(&a_dst[hh * 64 + o]), d);
    }
    g_s[bh * NN + n] = s;
    g_d[bh * NN + n] = d;
}

// ---------------- K2b: dmax, E12, P12 ---------------------------------------
__global__ __launch_bounds__(256) void compute_EP() {
    __shared__ float red[256];
    int bh = blockIdx.x;
    int tid = threadIdx.x;
    int base = bh << 10;
    float dm = -1e30f;
    #pragma unroll
    for (int k = 0; k < 4; k++) dm = fmaxf(dm, g_d[base + tid + 256 * k]);
    red[tid] = dm;
    __syncthreads();
    for (int off = 128; off > 0; off >>= 1) {
        if (tid < off) red[tid] = fmaxf(red[tid], red[tid + off]);
        __syncthreads();
    }
    float dmax = red[0];
    #pragma unroll
    for (int k = 0; k < 4; k++) {
        int i = base + tid + 256 * k;
        float dd = g_d[i] - dmax;
        g_E12[i] = make_float2(expf(dd), expf(0.2f * dd));
        float t = g_s[i] + dmax;
        float C = fmaxf(t, 0.2f * t);
        g_P12[i] = make_float2(expf(t - C), expf(0.2f * t - C));
    }
}

// ---------------- K3: mma.sync tf32 masked-softmax attention ----------------
// Per CTA: bh, 128 n-rows. 8 warps, warp w owns rows [w*16, w*16+16), all 64 o.
// weight(n,m) = adj ? tf32(max(P1[n]E1[m], P2[n]E2[m])) : 0, built in A-fragment
// registers; Z row-sums via an extra mma against a ones-column.
#define HSTR 72   // [m][o] smem stride; 72%32==8 -> conflict-free B-frag LDS

__global__ __launch_bounds__(256) void attn_mma() {
    __shared__ float2 E12s[NN];                 // 8 KB
    __shared__ u32 abS[128 * 33];               // 16.9 KB
    __shared__ float HsHi[32 * HSTR];           // 9.2 KB
    __shared__ float HsLo[32 * HSTR];           // 9.2 KB

    int tid = threadIdx.x, w = tid >> 5, l = tid & 31;
    int n0 = blockIdx.x << 7;                   // 8 n-tiles of 128
    int bh = blockIdx.y;
    int b = bh >> 3;

    for (int i = tid; i < NN; i += 256) E12s[i] = g_E12[bh * NN + i];
    for (int j = tid; j < 128 * 32; j += 256) {
        int r = j >> 5, wd = j & 31;
        abS[r * 33 + wd] = g_Abits[(size_t)(b * NN + n0 + r) * 32 + wd];
    }

    int l4 = l & 3, lg = l >> 2;
    int r0 = w * 16 + lg;                       // local n-rows r0, r0+8
    u64 pq0 = *(const u64*)&g_P12[bh * NN + n0 + r0];
    u64 pq1 = *(const u64*)&g_P12[bh * NN + n0 + r0 + 8];

    float acc[8][4];
    #pragma unroll
    for (int f = 0; f < 8; f++)
        #pragma unroll
        for (int i = 0; i < 4; i++) acc[f][i] = 0.f;
    float zacc[4] = {0.f, 0.f, 0.f, 0.f};
    const u32 one = 0x3f800000u;                // 1.0f (exact in tf32)

    // H-chunk loader identity
    int lo_o = tid & 63, lo_mq = (tid >> 6) << 3;
    const float* hrow = &g_hT[((size_t)bh * FOO + lo_o) * NN];

    for (int chunk = 0; chunk < 32; chunk++) {
        __syncthreads();
        {   // load H[m0..m0+31][all o] -> smem [m][o], split tf32 hi + residual
            int m0 = chunk << 5;
            float4 v1 = *(const float4*)&hrow[m0 + lo_mq];
            float4 v2 = *(const float4*)&hrow[m0 + lo_mq + 4];
            float vv[8] = {v1.x, v1.y, v1.z, v1.w, v2.x, v2.y, v2.z, v2.w};
            #pragma unroll
            for (int j = 0; j < 8; j++) {
                float hi = tf32rn(vv[j]);
                HsHi[(lo_mq + j) * HSTR + lo_o] = hi;
                HsLo[(lo_mq + j) * HSTR + lo_o] = vv[j] - hi;
            }
        }
        __syncthreads();

        u32 wd0 = abS[r0 * 33 + chunk];
        u32 wd1 = abS[(r0 + 8) * 33 + chunk];

        #pragma unroll
        for (int kc = 0; kc < 4; kc++) {
            int mb = (kc << 3) + l4;            // m index in chunk, 0..27
            u64 ea = *(const u64*)&E12s[(chunk << 5) + mb];
            u64 eb = *(const u64*)&E12s[(chunk << 5) + mb + 4];
            float x1, x2;
            upk2(x1, x2, mul2(pq0, ea)); float w00 = fmaxf(x1, x2);
            upk2(x1, x2, mul2(pq1, ea)); float w10 = fmaxf(x1, x2);
            upk2(x1, x2, mul2(pq0, eb)); float w01 = fmaxf(x1, x2);
            upk2(x1, x2, mul2(pq1, eb)); float w11 = fmaxf(x1, x2);
            int sh = (kc << 3) + l4;
            u32 a0 = ((wd0 >> sh) & 1u)       ? tf32bits(w00) : 0u;
            u32 a1 = ((wd1 >> sh) & 1u)       ? tf32bits(w10) : 0u;
            u32 a2 = ((wd0 >> (sh + 4)) & 1u) ? tf32bits(w01) : 0u;
            u32 a3 = ((wd1 >> (sh + 4)) & 1u) ? tf32bits(w11) : 0u;

            mma_tf32(zacc, a0, a1, a2, a3, one, one);    // row sums

            const float* bhi = &HsHi[mb * HSTR + lg];
            const float* blo = &HsLo[mb * HSTR + lg];
            #pragma unroll
            for (int f = 0; f < 8; f++) {
                u32 b0 = __float_as_uint(bhi[f * 8]);
                u32 b1 = __float_as_uint(bhi[4 * HSTR + f * 8]);
                mma_tf32(acc[f], a0, a1, a2, a3, b0, b1);
                u32 c0 = __float_as_uint(blo[f * 8]);
                u32 c1 = __float_as_uint(blo[4 * HSTR + f * 8]);
                mma_tf32(acc[f], a0, a1, a2, a3, c0, c1);
            }
        }
    }

    // every lane of zacc[0]/zacc[2] holds the full row sum (ones-column B)
    float zi0 = (zacc[0] > 0.f) ? (1.f / zacc[0]) : 0.f;
    float zi2 = (zacc[2] > 0.f) ? (1.f / zacc[2]) : 0.f;
    size_t rb0 = ((size_t)bh * NN + n0 + r0) * 64;
    size_t rb1 = rb0 + (size_t)8 * 64;
    #pragma unroll
    for (int f = 0; f < 8; f++) {
        int c0 = (f << 3) + (l4 << 1);
        float2 v0 = make_float2(acc[f][0] * zi0, acc[f][1] * zi0);
        float2 v1 = make_float2(acc[f][2] * zi2, acc[f][3] * zi2);
        *(float2*)&g_hout[rb0 + c0] = v0;
        *(float2*)&g_hout[rb1 + c0] = v1;
    }
}

// ---------------- K4: mean over heads + bias + mask -------------------------
__global__ __launch_bounds__(256) void finalize(const float* __restrict__ mask,
                                                const float* __restrict__ bias,
                                                float* __restrict__ out) {
    int idx = blockIdx.x * 256 + threadIdx.x;
    int o = idx & 63;
    int n = (idx >> 6) & 1023;
    int b = idx >> 16;
    size_t base = ((size_t)(b * 8) * NN + n) * 64 + o;
    float s = 0.f;
    #pragma unroll
    for (int h = 0; h < 8; h++) s += g_hout[base + (size_t)h * NN * 64];
    out[idx] = (s * 0.125f + bias[o]) * mask[b * NN + n];
}

// ---------------- launch -----------------------------------------------------
extern "C" void kernel_launch(void* const* d_in, const int* in_sizes, int n_in,
                              void* d_out, int out_size) {
    const float* x       = (const float*)d_in[0];
    const int*   A       = (const int*)d_in[1];
    const float* mask    = (const float*)d_in[2];
    /* d_in[3] p_atten unused */
    const float* e_atten = (const float*)d_in[4];
    const float* Npost   = (const float*)d_in[5];
    const float* w       = (const float*)d_in[6];
    const float* a_src   = (const float*)d_in[7];
    const float* a_dst   = (const float*)d_in[8];
    const float* bias    = (const float*)d_in[9];
    float* out = (float*)d_out;

    pack_adj<<<1024, 256>>>(A);
    compute_hT<<<dim3(16, 8, 8), 256>>>(x, e_atten, Npost, w);
    compute_sd<<<256, 256>>>(a_src, a_dst);
    compute_EP<<<64, 256>>>();
    attn_mma<<<dim3(8, 64), 256>>>();
    finalize<<<2048, 256>>>(mask, bias, out);
}

// round 9
// speedup vs baseline: 1.7599x; 1.1769x over previous
#include <cuda_runtime.h>

#define BB 8
#define NN 1024
#define HH 8
#define FOO 64
#define FINN 256
#define BH (BB*HH)          // 64
#define ROWS (BH*NN)        // 65536

typedef unsigned long long u64;
typedef unsigned int u32;

// ---------------- f32x2 / misc helpers --------------------------------------
__device__ __forceinline__ u64 pk2(float lo, float hi) {
    u64 r;
    asm("mov.b64 %0, {%1, %2};" : "=l"(r)
        : "r"(__float_as_uint(lo)), "r"(__float_as_uint(hi)));
    return r;
}
__device__ __forceinline__ u64 dup2(float v) {
    u64 r; u32 u = __float_as_uint(v);
    asm("mov.b64 %0, {%1, %1};" : "=l"(r) : "r"(u));
    return r;
}
__device__ __forceinline__ void upk2(float& lo, float& hi, u64 v) {
    u32 a, b;
    asm("mov.b64 {%0, %1}, %2;" : "=r"(a), "=r"(b) : "l"(v));
    lo = __uint_as_float(a); hi = __uint_as_float(b);
}
__device__ __forceinline__ u64 fma2(u64 a, u64 b, u64 c) {
    u64 d;
    asm("fma.rn.f32x2 %0, %1, %2, %3;" : "=l"(d) : "l"(a), "l"(b), "l"(c));
    return d;
}
__device__ __forceinline__ u64 mul2(u64 a, u64 b) {
    u64 d;
    asm("mul.rn.f32x2 %0, %1, %2;" : "=l"(d) : "l"(a), "l"(b));
    return d;
}
// pack two f32 -> f16x2 {lo16=f16(lo), hi16=f16(hi)}
__device__ __forceinline__ u32 f16x2pk(float hi, float lo) {
    u32 r;
    asm("cvt.rn.f16x2.f32 %0, %1, %2;" : "=r"(r) : "f"(hi), "f"(lo));
    return r;
}
// round f32 to nearest f16, return as f32
__device__ __forceinline__ float f16round(float x) {
    float r;
    asm("{.reg .f16 h; cvt.rn.f16.f32 h, %1; cvt.f32.f16 %0, h;}"
        : "=f"(r) : "f"(x));
    return r;
}

// fp16 warp mma: D(16x8,f32) += A(16x16,f16) * B(16x8,f16)
__device__ __forceinline__ void mma_f16(float* d, u32 a0, u32 a1, u32 a2, u32 a3,
                                        u32 b0, u32 b1) {
    asm volatile(
        "mma.sync.aligned.m16n8k16.row.col.f32.f16.f16.f32 "
        "{%0,%1,%2,%3}, {%4,%5,%6,%7}, {%8,%9}, {%0,%1,%2,%3};"
        : "+f"(d[0]), "+f"(d[1]), "+f"(d[2]), "+f"(d[3])
        : "r"(a0), "r"(a1), "r"(a2), "r"(a3), "r"(b0), "r"(b1));
}

// ---------------- device scratch --------------------------------------------
__device__ float g_hT[BH * FOO * NN];   // hT[bh][o][n]  16.8 MB
__device__ float g_hout[ROWS * FOO];    // per-head output [bh][n][o]
__device__ float g_s[ROWS];
__device__ float g_d[ROWS];
__device__ float2 g_E12[ROWS];          // {E1,E2} interleaved
__device__ float2 g_P12[ROWS];          // {P1,P2} interleaved
__device__ u32 g_Abits[BB * NN * 32];

// ---------------- K0: pack adjacency ----------------------------------------
__global__ __launch_bounds__(256) void pack_adj(const int* __restrict__ A) {
    int warp = threadIdx.x >> 5, lane = threadIdx.x & 31;
    int row = blockIdx.x * 8 + warp;
    const int* arow = A + (size_t)row * NN;
    #pragma unroll 4
    for (int w = 0; w < 32; w++) {
        int v = arow[w * 32 + lane];
        unsigned bits = __ballot_sync(0xffffffffu, v > 0);
        if (lane == 0) g_Abits[row * 32 + w] = bits;
    }
}

// ---------------- K1: hT[bh][o][n] = sum_k w[h][k][o] * recx[b][n][k] -------
__global__ __launch_bounds__(256) void compute_hT(const float* __restrict__ x,
                                                  const float* __restrict__ e_atten,
                                                  const float* __restrict__ Npost,
                                                  const float* __restrict__ w) {
    __shared__ float As[16][64];    // w[k][o]
    __shared__ float Bs[16][64];    // recx[k][n]
    int n0 = blockIdx.x * 64;
    int hh = blockIdx.y;
    int b  = blockIdx.z;
    int tid = threadIdx.x;
    int ty = tid >> 4, tx = tid & 15;         // out: o = ty*4.., n = tx*4..
    int la_k = tid >> 4, la_o = (tid & 15) * 4;
    int lb_n = tid & 63, lb_k = (tid >> 6) * 4;

    u64 c2[4][2];
    #pragma unroll
    for (int i = 0; i < 4; i++) { c2[i][0] = 0ull; c2[i][1] = 0ull; }

    for (int k0 = 0; k0 < FINN; k0 += 16) {
        *(float4*)&As[la_k][la_o] =
            *(const float4*)&w[((size_t)(hh * FINN + k0 + la_k)) * FOO + la_o];
        float4 e  = *(const float4*)&e_atten[((size_t)(b * NN + n0 + lb_n)) * FINN + k0 + lb_k];
        float4 xv = *(const float4*)&x[b * FINN + k0 + lb_k];
        float4 np = *(const float4*)&Npost[(size_t)(n0 + lb_n) * FINN + k0 + lb_k];
        Bs[lb_k + 0][lb_n] = e.x * xv.x * np.x;
        Bs[lb_k + 1][lb_n] = e.y * xv.y * np.y;
        Bs[lb_k + 2][lb_n] = e.z * xv.z * np.z;
        Bs[lb_k + 3][lb_n] = e.w * xv.w * np.w;
        __syncthreads();
        #pragma unroll
        for (int k = 0; k < 16; k++) {
            float4 bv = *(float4*)&Bs[k][tx * 4];
            u64 b01 = pk2(bv.x, bv.y);
            u64 b23 = pk2(bv.z, bv.w);
            #pragma unroll
            for (int i = 0; i < 4; i++) {
                u64 ad = dup2(As[k][ty * 4 + i]);
                c2[i][0] = fma2(b01, ad, c2[i][0]);
                c2[i][1] = fma2(b23, ad, c2[i][1]);
            }
        }
        __syncthreads();
    }
    int bh = b * HH + hh;
    #pragma unroll
    for (int i = 0; i < 4; i++) {
        size_t off = ((size_t)(bh * FOO) + ty * 4 + i) * NN + n0 + tx * 4;
        float4 v;
        upk2(v.x, v.y, c2[i][0]);
        upk2(v.z, v.w, c2[i][1]);
        *(float4*)&g_hT[off] = v;
    }
}

// ---------------- K2a: s,d from hT ------------------------------------------
__global__ __launch_bounds__(256) void compute_sd(const float* __restrict__ a_src,
                                                  const float* __restrict__ a_dst) {
    int bh = blockIdx.x >> 2;
    int n = ((blockIdx.x & 3) << 8) + threadIdx.x;
    int hh = bh & 7;
    const float* hp = &g_hT[(size_t)bh * FOO * NN + n];
    float s = 0.f, d = 0.f;
    #pragma unroll 8
    for (int o = 0; o < 64; o++) {
        float hv = hp[(size_t)o * NN];
        s = fmaf(hv, __ldg(&a_src[hh * 64 + o]), s);
        d = fmaf(hv, __ldg(&a_dst[hh * 64 + o]), d);
    }
    g_s[bh * NN + n] = s;
    g_d[bh * NN + n] = d;
}

// ---------------- K2b: dmax, E12, P12 ---------------------------------------
__global__ __launch_bounds__(256) void compute_EP() {
    __shared__ float red[256];
    int bh = blockIdx.x;
    int tid = threadIdx.x;
    int base = bh << 10;
    float dm = -1e30f;
    #pragma unroll
    for (int k = 0; k < 4; k++) dm = fmaxf(dm, g_d[base + tid + 256 * k]);
    red[tid] = dm;
    __syncthreads();
    for (int off = 128; off > 0; off >>= 1) {
        if (tid < off) red[tid] = fmaxf(red[tid], red[tid + off]);
        __syncthreads();
    }
    float dmax = red[0];
    #pragma unroll
    for (int k = 0; k < 4; k++) {
        int i = base + tid + 256 * k;
        float dd = g_d[i] - dmax;
        g_E12[i] = make_float2(expf(dd), expf(0.2f * dd));
        float t = g_s[i] + dmax;
        float C = fmaxf(t, 0.2f * t);
        g_P12[i] = make_float2(expf(t - C), expf(0.2f * t - C));
    }
}

// ---------------- K3: fp16 m16n8k16 masked-softmax attention ----------------
// Per CTA: bh, 128 n-rows, 64 o. 8 warps, warp w owns rows [w*16, w*16+16).
// A = weight tile (fp16, built in registers, Z via ones-column mma — exactly
// consistent with the numerator's fp16 weights). B = h chunk, fp16 hi + lo
// residual (2 passes -> h effectively exact).
#define HP 20   // u32 stride of Hs rows [o][m-pair]; conflict-free for b0/b1

__global__ __launch_bounds__(256) void attn_mma() {
    __shared__ float2 E12s[NN];                 // 8 KB
    __shared__ u32 abS[128 * 33];               // 16.9 KB
    __shared__ u32 HhiS[64 * HP];               // 5 KB (f16x2, m-pairs)
    __shared__ u32 HloS[64 * HP];               // 5 KB

    int tid = threadIdx.x, w = tid >> 5, l = tid & 31;
    int n0 = blockIdx.x << 7;                   // 8 n-tiles of 128
    int bh = blockIdx.y;
    int b = bh >> 3;

    for (int i = tid; i < NN; i += 256) E12s[i] = g_E12[bh * NN + i];
    for (int j = tid; j < 128 * 32; j += 256) {
        int r = j >> 5, wd = j & 31;
        abS[r * 33 + wd] = g_Abits[(size_t)(b * NN + n0 + r) * 32 + wd];
    }

    int l4 = l & 3, lg = l >> 2;
    int r0 = w * 16 + lg;                       // local n-rows r0, r0+8
    u64 pq0 = *(const u64*)&g_P12[bh * NN + n0 + r0];
    u64 pq1 = *(const u64*)&g_P12[bh * NN + n0 + r0 + 8];

    float acc[8][4];
    #pragma unroll
    for (int f = 0; f < 8; f++)
        #pragma unroll
        for (int i = 0; i < 4; i++) acc[f][i] = 0.f;
    float zacc[4] = {0.f, 0.f, 0.f, 0.f};
    const u32 ONE2 = 0x3C003C00u;               // f16x2 {1.0, 1.0}

    // H-chunk loader identity: o = lo_o, m = m0 + lo_mq .. +7
    int lo_o = tid & 63, lo_mq = (tid >> 6) << 3;
    const float* hrow = &g_hT[((size_t)bh * FOO + lo_o) * NN];

    // shared-space f32x2 view of E12s (8-byte aligned loads only)
    const u64* E12u = (const u64*)E12s;

    for (int chunk = 0; chunk < 32; chunk++) {
        __syncthreads();
        {   // load H[m0..m0+31][all o] -> f16x2 hi + residual lo, [o][m-pair]
            int m0 = chunk << 5;
            float4 v1 = *(const float4*)&hrow[m0 + lo_mq];
            float4 v2 = *(const float4*)&hrow[m0 + lo_mq + 4];
            float vv[8] = {v1.x, v1.y, v1.z, v1.w, v2.x, v2.y, v2.z, v2.w};
            float rr[8];
            #pragma unroll
            for (int j = 0; j < 8; j++) rr[j] = vv[j] - f16round(vv[j]);
            int pbase = lo_o * HP + (lo_mq >> 1);
            #pragma unroll
            for (int p = 0; p < 4; p++) {
                HhiS[pbase + p] = f16x2pk(vv[2 * p + 1], vv[2 * p]);
                HloS[pbase + p] = f16x2pk(rr[2 * p + 1], rr[2 * p]);
            }
        }
        __syncthreads();

        u32 wd0 = abS[r0 * 33 + chunk];
        u32 wd1 = abS[(r0 + 8) * 33 + chunk];
        int m0 = chunk << 5;

        #pragma unroll
        for (int kc = 0; kc < 2; kc++) {
            int s0 = (kc << 4) + (l4 << 1);     // m-in-chunk of first col (even)
            u64 eA0 = E12u[m0 + s0];            // {E1,E2} at m
            u64 eA1 = E12u[m0 + s0 + 1];        // m+1
            u64 eB0 = E12u[m0 + s0 + 8];        // m+8
            u64 eB1 = E12u[m0 + s0 + 9];        // m+9
            float x1, x2;
            upk2(x1, x2, mul2(pq0, eA0)); float w00 = fmaxf(x1, x2);
            upk2(x1, x2, mul2(pq0, eA1)); float w01 = fmaxf(x1, x2);
            upk2(x1, x2, mul2(pq1, eA0)); float w10 = fmaxf(x1, x2);
            upk2(x1, x2, mul2(pq1, eA1)); float w11 = fmaxf(x1, x2);
            upk2(x1, x2, mul2(pq0, eB0)); float w02 = fmaxf(x1, x2);
            upk2(x1, x2, mul2(pq0, eB1)); float w03 = fmaxf(x1, x2);
            upk2(x1, x2, mul2(pq1, eB0)); float w12 = fmaxf(x1, x2);
            upk2(x1, x2, mul2(pq1, eB1)); float w13 = fmaxf(x1, x2);
            w00 = ((wd0 >> (s0 + 0)) & 1u) ? w00 : 0.f;
            w01 = ((wd0 >> (s0 + 1)) & 1u) ? w01 : 0.f;
            w02 = ((wd0 >> (s0 + 8)) & 1u) ? w02 : 0.f;
            w03 = ((wd0 >> (s0 + 9)) & 1u) ? w03 : 0.f;
            w10 = ((wd1 >> (s0 + 0)) & 1u) ? w10 : 0.f;
            w11 = ((wd1 >> (s0 + 1)) & 1u) ? w11 : 0.f;
            w12 = ((wd1 >> (s0 + 8)) & 1u) ? w12 : 0.f;
            w13 = ((wd1 >> (s0 + 9)) & 1u) ? w13 : 0.f;
            u32 a0 = f16x2pk(w01, w00);         // {A[g][2t], A[g][2t+1]}
            u32 a1 = f16x2pk(w11, w10);         // row g+8
            u32 a2 = f16x2pk(w03, w02);         // cols 2t+8, 2t+9
            u32 a3 = f16x2pk(w13, w12);

            mma_f16(zacc, a0, a1, a2, a3, ONE2, ONE2);   // exact row sums

            int pb = (kc << 3) + l4;            // m-pair index: b0 at pb, b1 at pb+4
            #pragma unroll
            for (int f = 0; f < 8; f++) {
                int ob = (f * 8 + lg) * HP;
                mma_f16(acc[f], a0, a1, a2, a3, HhiS[ob + pb], HhiS[ob + pb + 4]);
                mma_f16(acc[f], a0, a1, a2, a3, HloS[ob + pb], HloS[ob + pb + 4]);
            }
        }
    }

    // every lane of zacc[0]/zacc[2] holds its row's full sum (ones-column B)
    float zi0 = (zacc[0] > 0.f) ? (1.f / zacc[0]) : 0.f;
    float zi2 = (zacc[2] > 0.f) ? (1.f / zacc[2]) : 0.f;
    size_t rb0 = ((size_t)bh * NN + n0 + r0) * 64;
    size_t rb1 = rb0 + (size_t)8 * 64;
    #pragma unroll
    for (int f = 0; f < 8; f++) {
        int c0 = (f << 3) + (l4 << 1);
        float2 v0 = make_float2(acc[f][0] * zi0, acc[f][1] * zi0);
        float2 v1 = make_float2(acc[f][2] * zi2, acc[f][3] * zi2);
        *(float2*)&g_hout[rb0 + c0] = v0;
        *(float2*)&g_hout[rb1 + c0] = v1;
    }
}

// ---------------- K4: mean over heads + bias + mask -------------------------
__global__ __launch_bounds__(256) void finalize(const float* __restrict__ mask,
                                                const float* __restrict__ bias,
                                                float* __restrict__ out) {
    int idx = blockIdx.x * 256 + threadIdx.x;
    int o = idx & 63;
    int n = (idx >> 6) & 1023;
    int b = idx >> 16;
    size_t base = ((size_t)(b * 8) * NN + n) * 64 + o;
    float s = 0.f;
    #pragma unroll
    for (int h = 0; h < 8; h++) s += g_hout[base + (size_t)h * NN * 64];
    out[idx] = (s * 0.125f + bias[o]) * mask[b * NN + n];
}

// ---------------- launch -----------------------------------------------------
extern "C" void kernel_launch(void* const* d_in, const int* in_sizes, int n_in,
                              void* d_out, int out_size) {
    const float* x       = (const float*)d_in[0];
    const int*   A       = (const int*)d_in[1];
    const float* mask    = (const float*)d_in[2];
    /* d_in[3] p_atten unused */
    const float* e_atten = (const float*)d_in[4];
    const float* Npost   = (const float*)d_in[5];
    const float* w       = (const float*)d_in[6];
    const float* a_src   = (const float*)d_in[7];
    const float* a_dst   = (const float*)d_in[8];
    const float* bias    = (const float*)d_in[9];
    float* out = (float*)d_out;

    pack_adj<<<1024, 256>>>(A);
    compute_hT<<<dim3(16, 8, 8), 256>>>(x, e_atten, Npost, w);
    compute_sd<<<256, 256>>>(a_src, a_dst);
    compute_EP<<<64, 256>>>();
    attn_mma<<<dim3(8, 64), 256>>>();
    finalize<<<2048, 256>>>(mask, bias, out);
}

// round 10
// speedup vs baseline: 2.0901x; 1.1876x over previous
#include <cuda_runtime.h>

#define BB 8
#define NN 1024
#define HH 8
#define FOO 64
#define FINN 256
#define BH (BB*HH)          // 64
#define ROWS (BH*NN)        // 65536

typedef unsigned long long u64;
typedef unsigned int u32;

// ---------------- f32x2 / misc helpers --------------------------------------
__device__ __forceinline__ u64 pk2(float lo, float hi) {
    u64 r;
    asm("mov.b64 %0, {%1, %2};" : "=l"(r)
        : "r"(__float_as_uint(lo)), "r"(__float_as_uint(hi)));
    return r;
}
__device__ __forceinline__ u64 dup2(float v) {
    u64 r; u32 u = __float_as_uint(v);
    asm("mov.b64 %0, {%1, %1};" : "=l"(r) : "r"(u));
    return r;
}
__device__ __forceinline__ void upk2(float& lo, float& hi, u64 v) {
    u32 a, b;
    asm("mov.b64 {%0, %1}, %2;" : "=r"(a), "=r"(b) : "l"(v));
    lo = __uint_as_float(a); hi = __uint_as_float(b);
}
__device__ __forceinline__ u64 fma2(u64 a, u64 b, u64 c) {
    u64 d;
    asm("fma.rn.f32x2 %0, %1, %2, %3;" : "=l"(d) : "l"(a), "l"(b), "l"(c));
    return d;
}
__device__ __forceinline__ u64 mul2(u64 a, u64 b) {
    u64 d;
    asm("mul.rn.f32x2 %0, %1, %2;" : "=l"(d) : "l"(a), "l"(b));
    return d;
}
// pack two f32 -> f16x2 {lo16=f16(lo), hi16=f16(hi)}
__device__ __forceinline__ u32 f16x2pk(float hi, float lo) {
    u32 r;
    asm("cvt.rn.f16x2.f32 %0, %1, %2;" : "=r"(r) : "f"(hi), "f"(lo));
    return r;
}

// fp16 warp mma: D(16x8,f32) += A(16x16,f16) * B(16x8,f16)
__device__ __forceinline__ void mma_f16(float* d, u32 a0, u32 a1, u32 a2, u32 a3,
                                        u32 b0, u32 b1) {
    asm volatile(
        "mma.sync.aligned.m16n8k16.row.col.f32.f16.f16.f32 "
        "{%0,%1,%2,%3}, {%4,%5,%6,%7}, {%8,%9}, {%0,%1,%2,%3};"
        : "+f"(d[0]), "+f"(d[1]), "+f"(d[2]), "+f"(d[3])
        : "r"(a0), "r"(a1), "r"(a2), "r"(a3), "r"(b0), "r"(b1));
}

// ---------------- device scratch --------------------------------------------
__device__ float g_hT[BH * FOO * NN];   // hT[bh][o][n]  16.8 MB
__device__ float g_hout[ROWS * FOO];    // per-head output [bh][n][o]
__device__ float g_s[ROWS];
__device__ float g_d[ROWS];
__device__ float2 g_E12[ROWS];          // {E1,E2} interleaved
__device__ float2 g_P12[ROWS];          // {P1,P2} interleaved
__device__ u32 g_Abits[BB * NN * 32];

// ---------------- K0: pack adjacency ----------------------------------------
__global__ __launch_bounds__(256) void pack_adj(const int* __restrict__ A) {
    int warp = threadIdx.x >> 5, lane = threadIdx.x & 31;
    int row = blockIdx.x * 8 + warp;
    const int* arow = A + (size_t)row * NN;
    #pragma unroll 4
    for (int w = 0; w < 32; w++) {
        int v = arow[w * 32 + lane];
        unsigned bits = __ballot_sync(0xffffffffu, v > 0);
        if (lane == 0) g_Abits[row * 32 + w] = bits;
    }
}

// ---------------- K1: hT[bh][o][n] = sum_k w[h][k][o] * recx[b][n][k] -------
__global__ __launch_bounds__(256) void compute_hT(const float* __restrict__ x,
                                                  const float* __restrict__ e_atten,
                                                  const float* __restrict__ Npost,
                                                  const float* __restrict__ w) {
    __shared__ float As[16][64];    // w[k][o]
    __shared__ float Bs[16][64];    // recx[k][n]
    int n0 = blockIdx.x * 64;
    int hh = blockIdx.y;
    int b  = blockIdx.z;
    int tid = threadIdx.x;
    int ty = tid >> 4, tx = tid & 15;         // out: o = ty*4.., n = tx*4..
    int la_k = tid >> 4, la_o = (tid & 15) * 4;
    int lb_n = tid & 63, lb_k = (tid >> 6) * 4;

    u64 c2[4][2];
    #pragma unroll
    for (int i = 0; i < 4; i++) { c2[i][0] = 0ull; c2[i][1] = 0ull; }

    for (int k0 = 0; k0 < FINN; k0 += 16) {
        *(float4*)&As[la_k][la_o] =
            *(const float4*)&w[((size_t)(hh * FINN + k0 + la_k)) * FOO + la_o];
        float4 e  = *(const float4*)&e_atten[((size_t)(b * NN + n0 + lb_n)) * FINN + k0 + lb_k];
        float4 xv = *(const float4*)&x[b * FINN + k0 + lb_k];
        float4 np = *(const float4*)&Npost[(size_t)(n0 + lb_n) * FINN + k0 + lb_k];
        Bs[lb_k + 0][lb_n] = e.x * xv.x * np.x;
        Bs[lb_k + 1][lb_n] = e.y * xv.y * np.y;
        Bs[lb_k + 2][lb_n] = e.z * xv.z * np.z;
        Bs[lb_k + 3][lb_n] = e.w * xv.w * np.w;
        __syncthreads();
        #pragma unroll
        for (int k = 0; k < 16; k++) {
            float4 bv = *(float4*)&Bs[k][tx * 4];
            u64 b01 = pk2(bv.x, bv.y);
            u64 b23 = pk2(bv.z, bv.w);
            #pragma unroll
            for (int i = 0; i < 4; i++) {
                u64 ad = dup2(As[k][ty * 4 + i]);
                c2[i][0] = fma2(b01, ad, c2[i][0]);
                c2[i][1] = fma2(b23, ad, c2[i][1]);
            }
        }
        __syncthreads();
    }
    int bh = b * HH + hh;
    #pragma unroll
    for (int i = 0; i < 4; i++) {
        size_t off = ((size_t)(bh * FOO) + ty * 4 + i) * NN + n0 + tx * 4;
        float4 v;
        upk2(v.x, v.y, c2[i][0]);
        upk2(v.z, v.w, c2[i][1]);
        *(float4*)&g_hT[off] = v;
    }
}

// ---------------- K2a: s,d from hT ------------------------------------------
__global__ __launch_bounds__(256) void compute_sd(const float* __restrict__ a_src,
                                                  const float* __restrict__ a_dst) {
    int bh = blockIdx.x >> 2;
    int n = ((blockIdx.x & 3) << 8) + threadIdx.x;
    int hh = bh & 7;
    const float* hp = &g_hT[(size_t)bh * FOO * NN + n];
    float s = 0.f, d = 0.f;
    #pragma unroll 8
    for (int o = 0; o < 64; o++) {
        float hv = hp[(size_t)o * NN];
        s = fmaf(hv, __ldg(&a_src[hh * 64 + o]), s);
        d = fmaf(hv, __ldg(&a_dst[hh * 64 + o]), d);
    }
    g_s[bh * NN + n] = s;
    g_d[bh * NN + n] = d;
}

// ---------------- K2b: dmax, E12, P12 ---------------------------------------
__global__ __launch_bounds__(256) void compute_EP() {
    __shared__ float red[256];
    int bh = blockIdx.x;
    int tid = threadIdx.x;
    int base = bh << 10;
    float dm = -1e30f;
    #pragma unroll
    for (int k = 0; k < 4; k++) dm = fmaxf(dm, g_d[base + tid + 256 * k]);
    red[tid] = dm;
    __syncthreads();
    for (int off = 128; off > 0; off >>= 1) {
        if (tid < off) red[tid] = fmaxf(red[tid], red[tid + off]);
        __syncthreads();
    }
    float dmax = red[0];
    #pragma unroll
    for (int k = 0; k < 4; k++) {
        int i = base + tid + 256 * k;
        float dd = g_d[i] - dmax;
        g_E12[i] = make_float2(expf(dd), expf(0.2f * dd));
        float t = g_s[i] + dmax;
        float C = fmaxf(t, 0.2f * t);
        g_P12[i] = make_float2(expf(t - C), expf(0.2f * t - C));
    }
}

// ---------------- K3: fp16 m16n8k16 masked-softmax attention ----------------
// Per CTA: bh, 128 n-rows, 64 o. 8 warps, warp w owns rows [w*16, w*16+16).
// A = weight tile (fp16, built in registers; Z via ones-column mma — exactly
// consistent with the numerator's fp16 weights). B = h chunk in fp16 (single
// pass; h-rounding error averages out across the ~512-neighbor weighted mean).
#define HP 20   // u32 stride of Hs rows [o][m-pair]; conflict-free for b0/b1

__global__ __launch_bounds__(256) void attn_mma() {
    __shared__ float2 E12s[NN];                 // 8 KB
    __shared__ u32 abS[128 * 33];               // 16.9 KB
    __shared__ u32 HhiS[64 * HP];               // 5 KB (f16x2, m-pairs)

    int tid = threadIdx.x, w = tid >> 5, l = tid & 31;
    int n0 = blockIdx.x << 7;                   // 8 n-tiles of 128
    int bh = blockIdx.y;
    int b = bh >> 3;

    for (int i = tid; i < NN; i += 256) E12s[i] = g_E12[bh * NN + i];
    for (int j = tid; j < 128 * 32; j += 256) {
        int r = j >> 5, wd = j & 31;
        abS[r * 33 + wd] = g_Abits[(size_t)(b * NN + n0 + r) * 32 + wd];
    }

    int l4 = l & 3, lg = l >> 2;
    int r0 = w * 16 + lg;                       // local n-rows r0, r0+8
    u64 pq0 = *(const u64*)&g_P12[bh * NN + n0 + r0];
    u64 pq1 = *(const u64*)&g_P12[bh * NN + n0 + r0 + 8];

    float acc[8][4];
    #pragma unroll
    for (int f = 0; f < 8; f++)
        #pragma unroll
        for (int i = 0; i < 4; i++) acc[f][i] = 0.f;
    float zacc[4] = {0.f, 0.f, 0.f, 0.f};
    const u32 ONE2 = 0x3C003C00u;               // f16x2 {1.0, 1.0}

    // H-chunk loader identity: o = lo_o, m = m0 + lo_mq .. +7
    int lo_o = tid & 63, lo_mq = (tid >> 6) << 3;
    const float* hrow = &g_hT[((size_t)bh * FOO + lo_o) * NN];

    // shared-space f32x2 view of E12s (8-byte aligned loads only)
    const u64* E12u = (const u64*)E12s;

    for (int chunk = 0; chunk < 32; chunk++) {
        __syncthreads();
        {   // load H[m0..m0+31][all o] -> f16x2, layout [o][m-pair]
            int m0 = chunk << 5;
            float4 v1 = *(const float4*)&hrow[m0 + lo_mq];
            float4 v2 = *(const float4*)&hrow[m0 + lo_mq + 4];
            int pbase = lo_o * HP + (lo_mq >> 1);
            HhiS[pbase + 0] = f16x2pk(v1.y, v1.x);
            HhiS[pbase + 1] = f16x2pk(v1.w, v1.z);
            HhiS[pbase + 2] = f16x2pk(v2.y, v2.x);
            HhiS[pbase + 3] = f16x2pk(v2.w, v2.z);
        }
        __syncthreads();

        u32 wd0 = abS[r0 * 33 + chunk];
        u32 wd1 = abS[(r0 + 8) * 33 + chunk];
        int m0 = chunk << 5;

        #pragma unroll
        for (int kc = 0; kc < 2; kc++) {
            int s0 = (kc << 4) + (l4 << 1);     // m-in-chunk of first col (even)
            u64 eA0 = E12u[m0 + s0];            // {E1,E2} at m
            u64 eA1 = E12u[m0 + s0 + 1];        // m+1
            u64 eB0 = E12u[m0 + s0 + 8];        // m+8
            u64 eB1 = E12u[m0 + s0 + 9];        // m+9
            float x1, x2;
            upk2(x1, x2, mul2(pq0, eA0)); float w00 = fmaxf(x1, x2);
            upk2(x1, x2, mul2(pq0, eA1)); float w01 = fmaxf(x1, x2);
            upk2(x1, x2, mul2(pq1, eA0)); float w10 = fmaxf(x1, x2);
            upk2(x1, x2, mul2(pq1, eA1)); float w11 = fmaxf(x1, x2);
            upk2(x1, x2, mul2(pq0, eB0)); float w02 = fmaxf(x1, x2);
            upk2(x1, x2, mul2(pq0, eB1)); float w03 = fmaxf(x1, x2);
            upk2(x1, x2, mul2(pq1, eB0)); float w12 = fmaxf(x1, x2);
            upk2(x1, x2, mul2(pq1, eB1)); float w13 = fmaxf(x1, x2);
            w00 = ((wd0 >> (s0 + 0)) & 1u) ? w00 : 0.f;
            w01 = ((wd0 >> (s0 + 1)) & 1u) ? w01 : 0.f;
            w02 = ((wd0 >> (s0 + 8)) & 1u) ? w02 : 0.f;
            w03 = ((wd0 >> (s0 + 9)) & 1u) ? w03 : 0.f;
            w10 = ((wd1 >> (s0 + 0)) & 1u) ? w10 : 0.f;
            w11 = ((wd1 >> (s0 + 1)) & 1u) ? w11 : 0.f;
            w12 = ((wd1 >> (s0 + 8)) & 1u) ? w12 : 0.f;
            w13 = ((wd1 >> (s0 + 9)) & 1u) ? w13 : 0.f;
            u32 a0 = f16x2pk(w01, w00);         // {A[g][2t], A[g][2t+1]}
            u32 a1 = f16x2pk(w11, w10);         // row g+8
            u32 a2 = f16x2pk(w03, w02);         // cols 2t+8, 2t+9
            u32 a3 = f16x2pk(w13, w12);

            mma_f16(zacc, a0, a1, a2, a3, ONE2, ONE2);   // exact row sums

            int pb = (kc << 3) + l4;            // m-pair index: b0 at pb, b1 at pb+4
            #pragma unroll
            for (int f = 0; f < 8; f++) {
                int ob = (f * 8 + lg) * HP;
                mma_f16(acc[f], a0, a1, a2, a3, HhiS[ob + pb], HhiS[ob + pb + 4]);
            }
        }
    }

    // every lane of zacc[0]/zacc[2] holds its row's full sum (ones-column B)
    float zi0 = (zacc[0] > 0.f) ? (1.f / zacc[0]) : 0.f;
    float zi2 = (zacc[2] > 0.f) ? (1.f / zacc[2]) : 0.f;
    size_t rb0 = ((size_t)bh * NN + n0 + r0) * 64;
    size_t rb1 = rb0 + (size_t)8 * 64;
    #pragma unroll
    for (int f = 0; f < 8; f++) {
        int c0 = (f << 3) + (l4 << 1);
        float2 v0 = make_float2(acc[f][0] * zi0, acc[f][1] * zi0);
        float2 v1 = make_float2(acc[f][2] * zi2, acc[f][3] * zi2);
        *(float2*)&g_hout[rb0 + c0] = v0;
        *(float2*)&g_hout[rb1 + c0] = v1;
    }
}

// ---------------- K4: mean over heads + bias + mask -------------------------
__global__ __launch_bounds__(256) void finalize(const float* __restrict__ mask,
                                                const float* __restrict__ bias,
                                                float* __restrict__ out) {
    int idx = blockIdx.x * 256 + threadIdx.x;
    int o = idx & 63;
    int n = (idx >> 6) & 1023;
    int b = idx >> 16;
    size_t base = ((size_t)(b * 8) * NN + n) * 64 + o;
    float s = 0.f;
    #pragma unroll
    for (int h = 0; h < 8; h++) s += g_hout[base + (size_t)h * NN * 64];
    out[idx] = (s * 0.125f + bias[o]) * mask[b * NN + n];
}

// ---------------- launch -----------------------------------------------------
extern "C" void kernel_launch(void* const* d_in, const int* in_sizes, int n_in,
                              void* d_out, int out_size) {
    const float* x       = (const float*)d_in[0];
    const int*   A       = (const int*)d_in[1];
    const float* mask    = (const float*)d_in[2];
    /* d_in[3] p_atten unused */
    const float* e_atten = (const float*)d_in[4];
    const float* Npost   = (const float*)d_in[5];
    const float* w       = (const float*)d_in[6];
    const float* a_src   = (const float*)d_in[7];
    const float* a_dst   = (const float*)d_in[8];
    const float* bias    = (const float*)d_in[9];
    float* out = (float*)d_out;

    pack_adj<<<1024, 256>>>(A);
    compute_hT<<<dim3(16, 8, 8), 256>>>(x, e_atten, Npost, w);
    compute_sd<<<256, 256>>>(a_src, a_dst);
    compute_EP<<<64, 256>>>();
    attn_mma<<<dim3(8, 64), 256>>>();
    finalize<<<2048, 256>>>(mask, bias, out);
}

// round 12
// speedup vs baseline: 2.1374x; 1.0226x over previous
#include <cuda_runtime.h>

#define BB 8
#define NN 1024
#define HH 8
#define FOO 64
#define FINN 256
#define BH (BB*HH)          // 64
#define ROWS (BH*NN)        // 65536

typedef unsigned long long u64;
typedef unsigned int u32;

// ---------------- f32x2 / misc helpers --------------------------------------
__device__ __forceinline__ u64 pk2(float lo, float hi) {
    u64 r;
    asm("mov.b64 %0, {%1, %2};" : "=l"(r)
        : "r"(__float_as_uint(lo)), "r"(__float_as_uint(hi)));
    return r;
}
__device__ __forceinline__ u64 dup2(float v) {
    u64 r; u32 u = __float_as_uint(v);
    asm("mov.b64 %0, {%1, %1};" : "=l"(r) : "r"(u));
    return r;
}
__device__ __forceinline__ void upk2(float& lo, float& hi, u64 v) {
    u32 a, b;
    asm("mov.b64 {%0, %1}, %2;" : "=r"(a), "=r"(b) : "l"(v));
    lo = __uint_as_float(a); hi = __uint_as_float(b);
}
__device__ __forceinline__ u64 fma2(u64 a, u64 b, u64 c) {
    u64 d;
    asm("fma.rn.f32x2 %0, %1, %2, %3;" : "=l"(d) : "l"(a), "l"(b), "l"(c));
    return d;
}
__device__ __forceinline__ u64 mul2(u64 a, u64 b) {
    u64 d;
    asm("mul.rn.f32x2 %0, %1, %2;" : "=l"(d) : "l"(a), "l"(b));
    return d;
}
// pack two f32 -> f16x2 {lo16=f16(lo), hi16=f16(hi)}
__device__ __forceinline__ u32 f16x2pk(float hi, float lo) {
    u32 r;
    asm("cvt.rn.f16x2.f32 %0, %1, %2;" : "=r"(r) : "f"(hi), "f"(lo));
    return r;
}

// fp16 warp mma: D(16x8,f32) += A(16x16,f16) * B(16x8,f16)
__device__ __forceinline__ void mma_f16(float* d, u32 a0, u32 a1, u32 a2, u32 a3,
                                        u32 b0, u32 b1) {
    asm volatile(
        "mma.sync.aligned.m16n8k16.row.col.f32.f16.f16.f32 "
        "{%0,%1,%2,%3}, {%4,%5,%6,%7}, {%8,%9}, {%0,%1,%2,%3};"
        : "+f"(d[0]), "+f"(d[1]), "+f"(d[2]), "+f"(d[3])
        : "r"(a0), "r"(a1), "r"(a2), "r"(a3), "r"(b0), "r"(b1));
}

// ---------------- device scratch --------------------------------------------
__device__ float g_hT[BH * FOO * NN];   // hT[bh][o][n]  16.8 MB
__device__ float g_hout[ROWS * FOO];    // per-head output [bh][n][o]
__device__ float g_s[ROWS];
__device__ float g_d[ROWS];
__device__ float2 g_E12[ROWS];          // {E1,E2} interleaved
__device__ float2 g_P12[ROWS];          // {P1,P2} interleaved
__device__ u32 g_Abits[BB * NN * 32];

// ---------------- K0: pack adjacency ----------------------------------------
__global__ __launch_bounds__(256) void pack_adj(const int* __restrict__ A) {
    int warp = threadIdx.x >> 5, lane = threadIdx.x & 31;
    int row = blockIdx.x * 8 + warp;
    const int* arow = A + (size_t)row * NN;
    #pragma unroll 4
    for (int w = 0; w < 32; w++) {
        int v = arow[w * 32 + lane];
        unsigned bits = __ballot_sync(0xffffffffu, v > 0);
        if (lane == 0) g_Abits[row * 32 + w] = bits;
    }
}

// ---------------- K1: hT + fused s,d epilogue -------------------------------
// hT[bh][o][n] = sum_k w[h][k][o] * recx[b][n][k];  s/d = h @ a_src/a_dst
__global__ __launch_bounds__(256) void compute_hT(const float* __restrict__ x,
                                                  const float* __restrict__ e_atten,
                                                  const float* __restrict__ Npost,
                                                  const float* __restrict__ w,
                                                  const float* __restrict__ a_src,
                                                  const float* __restrict__ a_dst) {
    __shared__ float As[16][64];    // w[k][o]
    __shared__ float Bs[16][64];    // recx[k][n]
    __shared__ float sredS[64][17];
    __shared__ float dredS[64][17];
    int n0 = blockIdx.x * 64;
    int hh = blockIdx.y;
    int b  = blockIdx.z;
    int tid = threadIdx.x;
    int ty = tid >> 4, tx = tid & 15;         // out: o = ty*4.., n = tx*4..
    int la_k = tid >> 4, la_o = (tid & 15) * 4;
    int lb_n = tid & 63, lb_k = (tid >> 6) * 4;

    u64 c2[4][2];
    #pragma unroll
    for (int i = 0; i < 4; i++) { c2[i][0] = 0ull; c2[i][1] = 0ull; }

    for (int k0 = 0; k0 < FINN; k0 += 16) {
        *(float4*)&As[la_k][la_o] =
            *(const float4*)&w[((size_t)(hh * FINN + k0 + la_k)) * FOO + la_o];
        float4 e  = *(const float4*)&e_atten[((size_t)(b * NN + n0 + lb_n)) * FINN + k0 + lb_k];
        float4 xv = *(const float4*)&x[b * FINN + k0 + lb_k];
        float4 np = *(const float4*)&Npost[(size_t)(n0 + lb_n) * FINN + k0 + lb_k];
        Bs[lb_k + 0][lb_n] = e.x * xv.x * np.x;
        Bs[lb_k + 1][lb_n] = e.y * xv.y * np.y;
        Bs[lb_k + 2][lb_n] = e.z * xv.z * np.z;
        Bs[lb_k + 3][lb_n] = e.w * xv.w * np.w;
        __syncthreads();
        #pragma unroll
        for (int k = 0; k < 16; k++) {
            float4 bv = *(float4*)&Bs[k][tx * 4];
            u64 b01 = pk2(bv.x, bv.y);
            u64 b23 = pk2(bv.z, bv.w);
            #pragma unroll
            for (int i = 0; i < 4; i++) {
                u64 ad = dup2(As[k][ty * 4 + i]);
                c2[i][0] = fma2(b01, ad, c2[i][0]);
                c2[i][1] = fma2(b23, ad, c2[i][1]);
            }
        }
        __syncthreads();
    }
    int bh = b * HH + hh;
    // unpack h values, write hT
    float hv[4][4];    // [o-idx i][n-idx j]
    #pragma unroll
    for (int i = 0; i < 4; i++) {
        upk2(hv[i][0], hv[i][1], c2[i][0]);
        upk2(hv[i][2], hv[i][3], c2[i][1]);
        size_t off = ((size_t)(bh * FOO) + ty * 4 + i) * NN + n0 + tx * 4;
        float4 v; v.x = hv[i][0]; v.y = hv[i][1]; v.z = hv[i][2]; v.w = hv[i][3];
        *(float4*)&g_hT[off] = v;
    }
    // fused s,d: partials over this thread's 4 o's
    #pragma unroll
    for (int j = 0; j < 4; j++) {
        float sp = 0.f, dp = 0.f;
        #pragma unroll
        for (int i = 0; i < 4; i++) {
            float as_ = __ldg(&a_src[hh * 64 + ty * 4 + i]);
            float ad_ = __ldg(&a_dst[hh * 64 + ty * 4 + i]);
            sp = fmaf(hv[i][j], as_, sp);
            dp = fmaf(hv[i][j], ad_, dp);
        }
        sredS[tx * 4 + j][ty] = sp;
        dredS[tx * 4 + j][ty] = dp;
    }
    __syncthreads();
    if (tid < 64) {
        float s = 0.f;
        #pragma unroll
        for (int t = 0; t < 16; t++) s += sredS[tid][t];
        g_s[bh * NN + n0 + tid] = s;
    } else if (tid < 128) {
        int n = tid - 64;
        float d = 0.f;
        #pragma unroll
        for (int t = 0; t < 16; t++) d += dredS[n][t];
        g_d[bh * NN + n0 + n] = d;
    }
}

// ---------------- K2b: dmax, E12, P12 ---------------------------------------
__global__ __launch_bounds__(256) void compute_EP() {
    __shared__ float red[256];
    int bh = blockIdx.x;
    int tid = threadIdx.x;
    int base = bh << 10;
    float dm = -1e30f;
    #pragma unroll
    for (int k = 0; k < 4; k++) dm = fmaxf(dm, g_d[base + tid + 256 * k]);
    red[tid] = dm;
    __syncthreads();
    for (int off = 128; off > 0; off >>= 1) {
        if (tid < off) red[tid] = fmaxf(red[tid], red[tid + off]);
        __syncthreads();
    }
    float dmax = red[0];
    #pragma unroll
    for (int k = 0; k < 4; k++) {
        int i = base + tid + 256 * k;
        float dd = g_d[i] - dmax;
        g_E12[i] = make_float2(expf(dd), expf(0.2f * dd));
        float t = g_s[i] + dmax;
        float C = fmaxf(t, 0.2f * t);
        g_P12[i] = make_float2(expf(t - C), expf(0.2f * t - C));
    }
}

// ---------------- K3: fp16 m16n8k16 masked-softmax attention ----------------
// Per CTA: bh, 128 n-rows, 64 o. 8 warps, warp w owns rows [w*16, w*16+16).
// A = weight tile (fp16, in registers). Z = scalar sum of pre-rounding weights
// (consistency gap ~1e-5, negligible). Adjacency words from L1-resident gmem.
#define HP 20   // u32 stride of Hs rows [o][m-pair]; conflict-free for b0/b1

__global__ void __launch_bounds__(256) attn_mma() {
    __shared__ float2 E12s[NN];                 // 8 KB
    __shared__ u32 HhiS[64 * HP];               // 5 KB (f16x2, m-pairs)

    int tid = threadIdx.x, w = tid >> 5, l = tid & 31;
    int n0 = blockIdx.x << 7;                   // 8 n-tiles of 128
    int bh = blockIdx.y;
    int b = bh >> 3;

    for (int i = tid; i < NN; i += 256) E12s[i] = g_E12[bh * NN + i];

    int l4 = l & 3, lg = l >> 2;
    int r0 = w * 16 + lg;                       // local n-rows r0, r0+8
    u64 pq0 = *(const u64*)&g_P12[bh * NN + n0 + r0];
    u64 pq1 = *(const u64*)&g_P12[bh * NN + n0 + r0 + 8];
    const u32* ab0 = &g_Abits[(size_t)(b * NN + n0 + r0) * 32];
    const u32* ab1 = ab0 + 8 * 32;

    float acc[8][4];
    #pragma unroll
    for (int f = 0; f < 8; f++)
        #pragma unroll
        for (int i = 0; i < 4; i++) acc[f][i] = 0.f;
    float z0 = 0.f, z1 = 0.f;

    // H-chunk loader identity: o = lo_o, m = m0 + lo_mq .. +7
    int lo_o = tid & 63, lo_mq = (tid >> 6) << 3;
    const float* hrow = &g_hT[((size_t)bh * FOO + lo_o) * NN];

    // shared-space f32x2 view of E12s (8-byte aligned loads only)
    const u64* E12u = (const u64*)E12s;

    for (int chunk = 0; chunk < 32; chunk++) {
        __syncthreads();
        // adjacency words early (L1-resident line per row, latency hidden by gen)
        u32 wd0 = __ldg(&ab0[chunk]);
        u32 wd1 = __ldg(&ab1[chunk]);
        {   // load H[m0..m0+31][all o] -> f16x2, layout [o][m-pair]
            int m0 = chunk << 5;
            float4 v1 = *(const float4*)&hrow[m0 + lo_mq];
            float4 v2 = *(const float4*)&hrow[m0 + lo_mq + 4];
            int pbase = lo_o * HP + (lo_mq >> 1);
            HhiS[pbase + 0] = f16x2pk(v1.y, v1.x);
            HhiS[pbase + 1] = f16x2pk(v1.w, v1.z);
            HhiS[pbase + 2] = f16x2pk(v2.y, v2.x);
            HhiS[pbase + 3] = f16x2pk(v2.w, v2.z);
        }
        __syncthreads();

        int m0 = chunk << 5;
        #pragma unroll
        for (int kc = 0; kc < 2; kc++) {
            int s0 = (kc << 4) + (l4 << 1);     // m-in-chunk of first col (even)
            u64 eA0 = E12u[m0 + s0];            // {E1,E2} at m
            u64 eA1 = E12u[m0 + s0 + 1];        // m+1
            u64 eB0 = E12u[m0 + s0 + 8];        // m+8
            u64 eB1 = E12u[m0 + s0 + 9];        // m+9
            float x1, x2;
            upk2(x1, x2, mul2(pq0, eA0)); float w00 = fmaxf(x1, x2);
            upk2(x1, x2, mul2(pq0, eA1)); float w01 = fmaxf(x1, x2);
            upk2(x1, x2, mul2(pq1, eA0)); float w10 = fmaxf(x1, x2);
            upk2(x1, x2, mul2(pq1, eA1)); float w11 = fmaxf(x1, x2);
            upk2(x1, x2, mul2(pq0, eB0)); float w02 = fmaxf(x1, x2);
            upk2(x1, x2, mul2(pq0, eB1)); float w03 = fmaxf(x1, x2);
            upk2(x1, x2, mul2(pq1, eB0)); float w12 = fmaxf(x1, x2);
            upk2(x1, x2, mul2(pq1, eB1)); float w13 = fmaxf(x1, x2);
            w00 = ((wd0 >> (s0 + 0)) & 1u) ? w00 : 0.f;
            w01 = ((wd0 >> (s0 + 1)) & 1u) ? w01 : 0.f;
            w02 = ((wd0 >> (s0 + 8)) & 1u) ? w02 : 0.f;
            w03 = ((wd0 >> (s0 + 9)) & 1u) ? w03 : 0.f;
            w10 = ((wd1 >> (s0 + 0)) & 1u) ? w10 : 0.f;
            w11 = ((wd1 >> (s0 + 1)) & 1u) ? w11 : 0.f;
            w12 = ((wd1 >> (s0 + 8)) & 1u) ? w12 : 0.f;
            w13 = ((wd1 >> (s0 + 9)) & 1u) ? w13 : 0.f;
            z0 += (w00 + w01) + (w02 + w03);    // scalar row-sum partials
            z1 += (w10 + w11) + (w12 + w13);
            u32 a0 = f16x2pk(w01, w00);         // {A[g][2t], A[g][2t+1]}
            u32 a1 = f16x2pk(w11, w10);         // row g+8
            u32 a2 = f16x2pk(w03, w02);         // cols 2t+8, 2t+9
            u32 a3 = f16x2pk(w13, w12);

            int pb = (kc << 3) + l4;            // m-pair index: b0 at pb, b1 at pb+4
            #pragma unroll
            for (int f = 0; f < 8; f++) {
                int ob = (f * 8 + lg) * HP;
                mma_f16(acc[f], a0, a1, a2, a3, HhiS[ob + pb], HhiS[ob + pb + 4]);
            }
        }
    }

    // reduce Z over the 4 l4-lanes of each row group
    z0 += __shfl_xor_sync(0xffffffffu, z0, 1);
    z0 += __shfl_xor_sync(0xffffffffu, z0, 2);
    z1 += __shfl_xor_sync(0xffffffffu, z1, 1);
    z1 += __shfl_xor_sync(0xffffffffu, z1, 2);
    float zi0 = (z0 > 0.f) ? (1.f / z0) : 0.f;
    float zi2 = (z1 > 0.f) ? (1.f / z1) : 0.f;
    size_t rb0 = ((size_t)bh * NN + n0 + r0) * 64;
    size_t rb1 = rb0 + (size_t)8 * 64;
    #pragma unroll
    for (int f = 0; f < 8; f++) {
        int c0 = (f << 3) + (l4 << 1);
        float2 v0 = make_float2(acc[f][0] * zi0, acc[f][1] * zi0);
        float2 v1 = make_float2(acc[f][2] * zi2, acc[f][3] * zi2);
        *(float2*)&g_hout[rb0 + c0] = v0;
        *(float2*)&g_hout[rb1 + c0] = v1;
    }
}

// ---------------- K4: mean over heads + bias + mask -------------------------
__global__ __launch_bounds__(256) void finalize(const float* __restrict__ mask,
                                                const float* __restrict__ bias,
                                                float* __restrict__ out) {
    int idx = blockIdx.x * 256 + threadIdx.x;
    int o = idx & 63;
    int n = (idx >> 6) & 1023;
    int b = idx >> 16;
    size_t base = ((size_t)(b * 8) * NN + n) * 64 + o;
    float s = 0.f;
    #pragma unroll
    for (int h = 0; h < 8; h++) s += g_hout[base + (size_t)h * NN * 64];
    out[idx] = (s * 0.125f + bias[o]) * mask[b * NN + n];
}

// ---------------- launch -----------------------------------------------------
extern "C" void kernel_launch(void* const* d_in, const int* in_sizes, int n_in,
                              void* d_out, int out_size) {
    const float* x       = (const float*)d_in[0];
    const int*   A       = (const int*)d_in[1];
    const float* mask    = (const float*)d_in[2];
    /* d_in[3] p_atten unused */
    const float* e_atten = (const float*)d_in[4];
    const float* Npost   = (const float*)d_in[5];
    const float* w       = (const float*)d_in[6];
    const float* a_src   = (const float*)d_in[7];
    const float* a_dst   = (const float*)d_in[8];
    const float* bias    = (const float*)d_in[9];
    float* out = (float*)d_out;

    pack_adj<<<1024, 256>>>(A);
    compute_hT<<<dim3(16, 8, 8), 256>>>(x, e_atten, Npost, w, a_src, a_dst);
    compute_EP<<<64, 256>>>();
    attn_mma<<<dim3(8, 64), 256>>>();
    finalize<<<2048, 256>>>(mask, bias, out);
}